// round 3
// baseline (speedup 1.0000x reference)
#include <cuda_runtime.h>
#include <cstdint>

#define Bsz   4
#define Hdim  48
#define Wdim  48
#define Cdim  256
#define NH    8
#define Dh    32
#define Nseq  2304            // 48*48
#define ROWS  9216            // B * Nseq

// ---------------- scratch (no allocations allowed) ----------------
__device__ float g_q   [Bsz*NH*Nseq*Dh];   // head-major [b][h][n][d]
__device__ float g_k   [Bsz*NH*Nseq*Dh];
__device__ float g_v   [Bsz*NH*Nseq*Dh];
__device__ float g_lepe[ROWS*Cdim];        // [b*n][c]
__device__ float g_att [ROWS*Cdim];        // [b*n][c]

// =================================================================
// Kernel 1: fused Q/K/V projection GEMM + bias + k-scale + RoPE
// =================================================================
__global__ void qkv_kernel(const float* __restrict__ x,
                           const float* __restrict__ Wq, const float* __restrict__ bq,
                           const float* __restrict__ Wk, const float* __restrict__ bk,
                           const float* __restrict__ Wv, const float* __restrict__ bv,
                           const float* __restrict__ sn, const float* __restrict__ cs)
{
    const int which = blockIdx.z;                  // 0=q 1=k 2=v
    const float* Wm = (which==0) ? Wq : (which==1 ? Wk : Wv);
    const float* bm = (which==0) ? bq : (which==1 ? bk : bv);
    float* gout     = (which==0) ? g_q : (which==1 ? g_k : g_v);

    __shared__ float As[16][65];
    __shared__ float Bs[16][65];

    const int t  = threadIdx.x;          // 256 threads
    const int r0 = blockIdx.y * 64;
    const int c0 = blockIdx.x * 64;
    const int ty = t >> 4, tx = t & 15;

    float acc[4][4] = {};

    for (int k0 = 0; k0 < Cdim; k0 += 16) {
        {   // A tile: 64 rows x 16 k, float4 per thread
            int m  = t >> 2;
            int kq = (t & 3) * 4;
            float4 v4 = *(const float4*)(x + (size_t)(r0+m)*Cdim + k0 + kq);
            As[kq+0][m] = v4.x; As[kq+1][m] = v4.y;
            As[kq+2][m] = v4.z; As[kq+3][m] = v4.w;
        }
        #pragma unroll
        for (int l = 0; l < 4; l++) {   // B tile: 16 k x 64 cols
            int e  = t + l*256;
            int kk = e >> 6, cc = e & 63;
            Bs[kk][cc] = Wm[(size_t)(k0+kk)*Cdim + c0 + cc];
        }
        __syncthreads();
        #pragma unroll
        for (int kk = 0; kk < 16; kk++) {
            float a[4], b[4];
            #pragma unroll
            for (int i = 0; i < 4; i++) a[i] = As[kk][ty*4+i];
            #pragma unroll
            for (int j = 0; j < 4; j++) b[j] = Bs[kk][tx*4+j];
            #pragma unroll
            for (int i = 0; i < 4; i++)
                #pragma unroll
                for (int j = 0; j < 4; j++)
                    acc[i][j] += a[i]*b[j];
        }
        __syncthreads();
    }

    const float scaling = 0.17677669529663687f;    // 32^-0.5
    #pragma unroll
    for (int i = 0; i < 4; i++) {
        int r  = r0 + ty*4 + i;
        int b_ = r / Nseq;
        int n  = r % Nseq;
        int sbase = n * Dh;                        // sin/cos: [(h*48+w)*32 + dd]
        #pragma unroll
        for (int j = 0; j < 4; j += 2) {
            int ce = c0 + tx*4 + j;                // even column, pair (ce, ce+1)
            float ve = acc[i][j]   + bm[ce];
            float vo = acc[i][j+1] + bm[ce+1];
            if (which == 1) { ve *= scaling; vo *= scaling; }
            if (which < 2) {                       // RoPE on q and k
                int de = ce & 31;
                float se = sn[sbase+de],   c_e = cs[sbase+de];
                float so = sn[sbase+de+1], c_o = cs[sbase+de+1];
                float oe = ve*c_e - vo*se;         // x*cos + (-x2)*sin
                float oo = vo*c_o + ve*so;         // x*cos + ( x1)*sin
                ve = oe; vo = oo;
            }
            int head = ce >> 5;
            size_t idx = ((size_t)(b_*NH + head)*Nseq + n)*Dh + (ce & 31);
            gout[idx]   = ve;
            gout[idx+1] = vo;
        }
    }
}

// =================================================================
// Kernel 2: LePE — depthwise 5x5 conv over V (zero pad 2), + bias.
// =================================================================
__global__ void lepe_kernel(const float* __restrict__ dww, const float* __restrict__ dwb)
{
    int idx = blockIdx.x * blockDim.x + threadIdx.x;   // over ROWS*Cdim
    int c  = idx & 255;
    int p  = idx >> 8;
    int b_ = p / Nseq;
    int n  = p % Nseq;
    int hp = n / Wdim, wp = n % Wdim;
    int head = c >> 5, dd = c & 31;
    const float* vbase = g_v + ((size_t)(b_*NH + head)*Nseq)*Dh + dd;

    float acc = dwb[c];
    #pragma unroll
    for (int ky = 0; ky < 5; ky++) {
        int hh = hp + ky - 2;
        if (hh < 0 || hh >= Hdim) continue;
        #pragma unroll
        for (int kx = 0; kx < 5; kx++) {
            int ww = wp + kx - 2;
            if (ww < 0 || ww >= Wdim) continue;
            acc += vbase[(size_t)(hh*Wdim + ww)*Dh] * dww[(ky*5 + kx)*Cdim + c];
        }
    }
    g_lepe[idx] = acc;
}

// =================================================================
// Kernel 3: flash attention with additive mask.
//   grid (36 row-tiles, 8 heads, 4 batch), 64 threads = 64 query rows.
//   Mask tile is preloaded into Ss and scores computed in place
//   (static smem ~33KB, under the 48KB limit).
// =================================================================
__global__ void attn_kernel(const float* __restrict__ mask)
{
    const int rt   = blockIdx.x;     // 0..35
    const int head = blockIdx.y;
    const int b_   = blockIdx.z;
    const int t    = threadIdx.x;    // 0..63 (query row within tile)

    __shared__ __align__(16) float Ks[64*32];
    __shared__ __align__(16) float Vs[64*32];
    __shared__ float Ss[64*65];      // mask-then-score tile [qrow][kcol], padded

    const float* qb = g_q + ((size_t)(b_*NH + head)*Nseq + rt*64)*Dh;
    const float* kb = g_k + ((size_t)(b_*NH + head)*Nseq)*Dh;
    const float* vb = g_v + ((size_t)(b_*NH + head)*Nseq)*Dh;
    const float* mb = mask + ((size_t)head*Nseq + (size_t)rt*64)*Nseq;

    float q[32];
    #pragma unroll
    for (int dd = 0; dd < 32; dd++) q[dd] = qb[t*32 + dd];

    float o[32] = {};
    float mrun = -1e30f, lrun = 0.f;
    float* srow = Ss + t*65;

    for (int kt = 0; kt < Nseq/64; kt++) {
        const float* ksrc = kb + (size_t)kt*64*32;
        const float* vsrc = vb + (size_t)kt*64*32;
        #pragma unroll
        for (int l = 0; l < 32; l++) {        // 2048 floats, contiguous
            int e = t + l*64;
            Ks[e] = ksrc[e];
            Vs[e] = vsrc[e];
        }
        #pragma unroll
        for (int l = 0; l < 64; l++)          // mask rows, coalesced -> Ss
            Ss[l*65 + t] = mb[(size_t)l*Nseq + kt*64 + t];
        __syncthreads();

        // pass 1: scores (+mask already in Ss) + tile max, in place
        float tmax = -1e30f;
        #pragma unroll 4
        for (int j = 0; j < 64; j++) {
            const float4* k4 = (const float4*)(Ks + j*32);
            float s = 0.f;
            #pragma unroll
            for (int d4 = 0; d4 < 8; d4++) {
                float4 kv = k4[d4];
                s += q[d4*4+0]*kv.x + q[d4*4+1]*kv.y
                   + q[d4*4+2]*kv.z + q[d4*4+3]*kv.w;
            }
            s += srow[j];
            srow[j] = s;
            tmax = fmaxf(tmax, s);
        }
        float mnew = fmaxf(mrun, tmax);
        float corr = __expf(mrun - mnew);
        lrun *= corr;
        #pragma unroll
        for (int dd = 0; dd < 32; dd++) o[dd] *= corr;

        // pass 2: softmax-weighted V accumulation
        #pragma unroll 2
        for (int j = 0; j < 64; j++) {
            float p = __expf(srow[j] - mnew);
            lrun += p;
            const float4* v4 = (const float4*)(Vs + j*32);
            #pragma unroll
            for (int d4 = 0; d4 < 8; d4++) {
                float4 vv = v4[d4];
                o[d4*4+0] += p*vv.x; o[d4*4+1] += p*vv.y;
                o[d4*4+2] += p*vv.z; o[d4*4+3] += p*vv.w;
            }
        }
        mrun = mnew;
        __syncthreads();
    }

    float inv = 1.f / lrun;
    int n = rt*64 + t;
    float* ob = g_att + ((size_t)b_*Nseq + n)*Cdim + head*Dh;
    #pragma unroll
    for (int dd = 0; dd < 32; dd++) ob[dd] = o[dd]*inv;
}

// =================================================================
// Kernel 4: out = (att + lepe) @ Wo + bo  -> d_out [9216][256]
// =================================================================
__global__ void out_kernel(const float* __restrict__ Wo, const float* __restrict__ bo,
                           float* __restrict__ out)
{
    __shared__ float As[16][65];
    __shared__ float Bs[16][65];

    const int t  = threadIdx.x;
    const int r0 = blockIdx.y * 64;
    const int c0 = blockIdx.x * 64;
    const int ty = t >> 4, tx = t & 15;

    float acc[4][4] = {};

    for (int k0 = 0; k0 < Cdim; k0 += 16) {
        {
            int m  = t >> 2;
            int kq = (t & 3) * 4;
            size_t off = (size_t)(r0+m)*Cdim + k0 + kq;
            float4 a4 = *(const float4*)(g_att  + off);
            float4 l4 = *(const float4*)(g_lepe + off);
            As[kq+0][m] = a4.x + l4.x; As[kq+1][m] = a4.y + l4.y;
            As[kq+2][m] = a4.z + l4.z; As[kq+3][m] = a4.w + l4.w;
        }
        #pragma unroll
        for (int l = 0; l < 4; l++) {
            int e  = t + l*256;
            int kk = e >> 6, cc = e & 63;
            Bs[kk][cc] = Wo[(size_t)(k0+kk)*Cdim + c0 + cc];
        }
        __syncthreads();
        #pragma unroll
        for (int kk = 0; kk < 16; kk++) {
            float a[4], b[4];
            #pragma unroll
            for (int i = 0; i < 4; i++) a[i] = As[kk][ty*4+i];
            #pragma unroll
            for (int j = 0; j < 4; j++) b[j] = Bs[kk][tx*4+j];
            #pragma unroll
            for (int i = 0; i < 4; i++)
                #pragma unroll
                for (int j = 0; j < 4; j++)
                    acc[i][j] += a[i]*b[j];
        }
        __syncthreads();
    }

    #pragma unroll
    for (int i = 0; i < 4; i++) {
        int r = r0 + ty*4 + i;
        #pragma unroll
        for (int j = 0; j < 4; j++) {
            int c = c0 + tx*4 + j;
            out[(size_t)r*Cdim + c] = acc[i][j] + bo[c];
        }
    }
}

// =================================================================
extern "C" void kernel_launch(void* const* d_in, const int* in_sizes, int n_in,
                              void* d_out, int out_size)
{
    const float* x    = (const float*)d_in[0];
    const float* sn   = (const float*)d_in[1];
    const float* cs   = (const float*)d_in[2];
    const float* mask = (const float*)d_in[3];
    const float* Wq   = (const float*)d_in[4];
    const float* bq   = (const float*)d_in[5];
    const float* Wk   = (const float*)d_in[6];
    const float* bk   = (const float*)d_in[7];
    const float* Wv   = (const float*)d_in[8];
    const float* bv   = (const float*)d_in[9];
    const float* dww  = (const float*)d_in[10];
    const float* dwb  = (const float*)d_in[11];
    const float* Wo   = (const float*)d_in[12];
    const float* bo   = (const float*)d_in[13];
    // d_in[14] = num_heads (constant 8, hardcoded)

    dim3 g1(Cdim/64, ROWS/64, 3);
    qkv_kernel<<<g1, 256>>>(x, Wq, bq, Wk, bk, Wv, bv, sn, cs);

    lepe_kernel<<<(ROWS*Cdim)/256, 256>>>(dww, dwb);

    dim3 g3(Nseq/64, NH, Bsz);
    attn_kernel<<<g3, 64>>>(mask);

    dim3 g4(Cdim/64, ROWS/64);
    out_kernel<<<g4, 256>>>(Wo, bo, (float*)d_out);
}

// round 5
// speedup vs baseline: 3.0060x; 3.0060x over previous
#include <cuda_runtime.h>
#include <cuda_bf16.h>
#include <cstdint>

#define Bsz   4
#define Hdim  48
#define Wdim  48
#define Cdim  256
#define NH    8
#define Dh    32
#define Nseq  2304            // 48*48
#define ROWS  9216            // B * Nseq

// ---------------- scratch (no allocations allowed) ----------------
__device__ __nv_bfloat16 g_qh[Bsz*NH*Nseq*Dh];   // head-major bf16 (RoPE'd)
__device__ __nv_bfloat16 g_kh[Bsz*NH*Nseq*Dh];   // head-major bf16 (RoPE'd, pre-scaled)
__device__ __nv_bfloat16 g_vh[Bsz*NH*Nseq*Dh];   // head-major bf16
__device__ float g_v   [Bsz*NH*Nseq*Dh];         // fp32 V for LePE
__device__ float g_lepe[ROWS*Cdim];              // [b*n][c]
__device__ float g_att [ROWS*Cdim];              // [b*n][c]

// ---------------- helpers ----------------
__device__ __forceinline__ void mma_bf16(float& d0, float& d1, float& d2, float& d3,
                                         uint32_t a0, uint32_t a1, uint32_t a2, uint32_t a3,
                                         uint32_t b0, uint32_t b1)
{
    asm volatile("mma.sync.aligned.m16n8k16.row.col.f32.bf16.bf16.f32 "
                 "{%0,%1,%2,%3}, {%4,%5,%6,%7}, {%8,%9}, {%0,%1,%2,%3};"
                 : "+f"(d0), "+f"(d1), "+f"(d2), "+f"(d3)
                 : "r"(a0), "r"(a1), "r"(a2), "r"(a3), "r"(b0), "r"(b1));
}

__device__ __forceinline__ uint32_t packbf(float lo, float hi)
{
    uint32_t r;
    asm("cvt.rn.bf16x2.f32 %0, %1, %2;" : "=r"(r) : "f"(hi), "f"(lo));
    return r;
}

// =================================================================
// Kernel 1: fused Q/K/V projection GEMM + bias + k-scale + RoPE
//   q,k -> bf16 head-major (RoPE'd); v -> fp32 (LePE) + bf16 (attn)
// =================================================================
__global__ void qkv_kernel(const float* __restrict__ x,
                           const float* __restrict__ Wq, const float* __restrict__ bq,
                           const float* __restrict__ Wk, const float* __restrict__ bk,
                           const float* __restrict__ Wv, const float* __restrict__ bv,
                           const float* __restrict__ sn, const float* __restrict__ cs)
{
    const int which = blockIdx.z;                  // 0=q 1=k 2=v
    const float* Wm = (which==0) ? Wq : (which==1 ? Wk : Wv);
    const float* bm = (which==0) ? bq : (which==1 ? bk : bv);

    __shared__ float As[16][65];
    __shared__ float Bs[16][65];

    const int t  = threadIdx.x;          // 256 threads
    const int r0 = blockIdx.y * 64;
    const int c0 = blockIdx.x * 64;
    const int ty = t >> 4, tx = t & 15;

    float acc[4][4] = {};

    for (int k0 = 0; k0 < Cdim; k0 += 16) {
        {   // A tile: 64 rows x 16 k, float4 per thread
            int m  = t >> 2;
            int kq = (t & 3) * 4;
            float4 v4 = *(const float4*)(x + (size_t)(r0+m)*Cdim + k0 + kq);
            As[kq+0][m] = v4.x; As[kq+1][m] = v4.y;
            As[kq+2][m] = v4.z; As[kq+3][m] = v4.w;
        }
        #pragma unroll
        for (int l = 0; l < 4; l++) {   // B tile: 16 k x 64 cols
            int e  = t + l*256;
            int kk = e >> 6, cc = e & 63;
            Bs[kk][cc] = Wm[(size_t)(k0+kk)*Cdim + c0 + cc];
        }
        __syncthreads();
        #pragma unroll
        for (int kk = 0; kk < 16; kk++) {
            float a[4], b[4];
            #pragma unroll
            for (int i = 0; i < 4; i++) a[i] = As[kk][ty*4+i];
            #pragma unroll
            for (int j = 0; j < 4; j++) b[j] = Bs[kk][tx*4+j];
            #pragma unroll
            for (int i = 0; i < 4; i++)
                #pragma unroll
                for (int j = 0; j < 4; j++)
                    acc[i][j] += a[i]*b[j];
        }
        __syncthreads();
    }

    const float scaling = 0.17677669529663687f;    // 32^-0.5
    #pragma unroll
    for (int i = 0; i < 4; i++) {
        int r  = r0 + ty*4 + i;
        int b_ = r / Nseq;
        int n  = r % Nseq;
        int sbase = n * Dh;
        #pragma unroll
        for (int j = 0; j < 4; j += 2) {
            int ce = c0 + tx*4 + j;                // even column, pair (ce, ce+1)
            float ve = acc[i][j]   + bm[ce];
            float vo = acc[i][j+1] + bm[ce+1];
            if (which == 1) { ve *= scaling; vo *= scaling; }
            if (which < 2) {                       // RoPE on q and k
                int de = ce & 31;
                float se = sn[sbase+de],   c_e = cs[sbase+de];
                float so = sn[sbase+de+1], c_o = cs[sbase+de+1];
                float oe = ve*c_e - vo*se;
                float oo = vo*c_o + ve*so;
                ve = oe; vo = oo;
            }
            int head = ce >> 5;
            size_t idx = ((size_t)(b_*NH + head)*Nseq + n)*Dh + (ce & 31);
            __nv_bfloat162 h;
            h.x = __float2bfloat16_rn(ve);
            h.y = __float2bfloat16_rn(vo);
            if (which == 0) {
                *(__nv_bfloat162*)(g_qh + idx) = h;
            } else if (which == 1) {
                *(__nv_bfloat162*)(g_kh + idx) = h;
            } else {
                *(float2*)(g_v + idx) = make_float2(ve, vo);
                *(__nv_bfloat162*)(g_vh + idx) = h;
            }
        }
    }
}

// =================================================================
// Kernel 2: LePE — depthwise 5x5 conv over V (zero pad 2), + bias.
// =================================================================
__global__ void lepe_kernel(const float* __restrict__ dww, const float* __restrict__ dwb)
{
    int idx = blockIdx.x * blockDim.x + threadIdx.x;   // over ROWS*Cdim
    int c  = idx & 255;
    int p  = idx >> 8;
    int b_ = p / Nseq;
    int n  = p % Nseq;
    int hp = n / Wdim, wp = n % Wdim;
    int head = c >> 5, dd = c & 31;
    const float* vbase = g_v + ((size_t)(b_*NH + head)*Nseq)*Dh + dd;

    float acc = dwb[c];
    #pragma unroll
    for (int ky = 0; ky < 5; ky++) {
        int hh = hp + ky - 2;
        if (hh < 0 || hh >= Hdim) continue;
        #pragma unroll
        for (int kx = 0; kx < 5; kx++) {
            int ww = wp + kx - 2;
            if (ww < 0 || ww >= Wdim) continue;
            acc += vbase[(size_t)(hh*Wdim + ww)*Dh] * dww[(ky*5 + kx)*Cdim + c];
        }
    }
    g_lepe[idx] = acc;
}

// =================================================================
// Kernel 3: flash attention, bf16 tensor-core mma (m16n8k16).
//   grid (Bsz*36, NH), 128 threads = 4 warps, warp w owns q-rows w*16..+15.
//   Per 64-key tile: mask loaded straight into mma accumulators (C-init),
//   K staged [64][36] bf16, V staged transposed [32][72] bf16,
//   online softmax in registers, P kept in registers as bf16 A-frags.
// =================================================================
__global__ void __launch_bounds__(128) attn_kernel(const float* __restrict__ mask)
{
    const int bx   = blockIdx.x;
    const int b_   = bx & 3;         // batch fastest -> mask L2 reuse across b
    const int rt   = bx >> 2;        // 0..35 q-row tile
    const int head = blockIdx.y;
    const int t    = threadIdx.x;
    const int w    = t >> 5;         // warp 0..3
    const int lane = t & 31;
    const int g    = lane >> 2;      // 0..7
    const int tig  = lane & 3;       // 0..3

    __shared__ __align__(16) __nv_bfloat16 Qs[64][36];
    __shared__ __align__(16) __nv_bfloat16 Ks[64][36];
    __shared__ __align__(16) __nv_bfloat16 Vt[32][72];

    const size_t hb = (size_t)(b_*NH + head);
    const uint32_t* qg  = (const uint32_t*)(g_qh + (hb*Nseq + (size_t)rt*64)*Dh);
    const uint32_t* kg0 = (const uint32_t*)(g_kh + hb*Nseq*Dh);
    const uint32_t* vg0 = (const uint32_t*)(g_vh + hb*Nseq*Dh);
    const float* mrow0 = mask + ((size_t)head*Nseq + rt*64 + w*16 + g)*Nseq;
    const float* mrow8 = mrow0 + 8*(size_t)Nseq;

    // ---- stage Q once ----
    uint32_t* qs_u = (uint32_t*)Qs;            // row stride 18 u32
    uint32_t* ks_u = (uint32_t*)Ks;
    #pragma unroll
    for (int l = 0; l < 8; l++) {
        int e = t + l*128;
        qs_u[(e >> 4)*18 + (e & 15)] = qg[e];
    }
    __syncthreads();

    // Q A-fragments (2 k-steps of 16 over d=32)
    uint32_t qa[2][4];
    #pragma unroll
    for (int ks = 0; ks < 2; ks++) {
        const uint32_t* r0 = qs_u + (w*16+g  )*18 + ks*8 + tig;
        const uint32_t* r8 = qs_u + (w*16+g+8)*18 + ks*8 + tig;
        qa[ks][0] = r0[0]; qa[ks][1] = r8[0];
        qa[ks][2] = r0[4]; qa[ks][3] = r8[4];
    }

    float o[4][4] = {};                  // O: 4 d-frags (m16n8), fp32
    float m0 = -1e30f, m1 = -1e30f;
    float l0 = 0.f,    l1 = 0.f;

    for (int kt = 0; kt < Nseq/64; kt++) {
        // ---- mask tile -> accumulator init (C of the S mma) ----
        float s[8][4];
        #pragma unroll
        for (int j = 0; j < 8; j++) {
            float2 mA = *(const float2*)(mrow0 + (size_t)kt*64 + j*8 + 2*tig);
            float2 mB = *(const float2*)(mrow8 + (size_t)kt*64 + j*8 + 2*tig);
            s[j][0] = mA.x; s[j][1] = mA.y; s[j][2] = mB.x; s[j][3] = mB.y;
        }
        // ---- stage K (row-major) and V (transposed) ----
        const uint32_t* kg = kg0 + (size_t)kt*64*16;
        const uint32_t* vg = vg0 + (size_t)kt*64*16;
        #pragma unroll
        for (int l = 0; l < 8; l++) {
            int e   = t + l*128;
            int row = e >> 4, dp = e & 15;
            ks_u[row*18 + dp] = kg[e];
            uint32_t vv = vg[e];
            __nv_bfloat162 v2 = *(__nv_bfloat162*)&vv;
            Vt[2*dp  ][row] = v2.x;
            Vt[2*dp+1][row] = v2.y;
        }
        __syncthreads();

        // ---- S = Q K^T + mask : 8 key-frags x 2 k-steps ----
        #pragma unroll
        for (int j = 0; j < 8; j++) {
            #pragma unroll
            for (int ks = 0; ks < 2; ks++) {
                const uint32_t* kr = ks_u + (j*8+g)*18 + ks*8 + tig;
                mma_bf16(s[j][0], s[j][1], s[j][2], s[j][3],
                         qa[ks][0], qa[ks][1], qa[ks][2], qa[ks][3],
                         kr[0], kr[4]);
            }
        }

        // ---- online softmax (rows g and g+8, quad-reduced) ----
        float t0 = -1e30f, t1 = -1e30f;
        #pragma unroll
        for (int j = 0; j < 8; j++) {
            t0 = fmaxf(t0, fmaxf(s[j][0], s[j][1]));
            t1 = fmaxf(t1, fmaxf(s[j][2], s[j][3]));
        }
        t0 = fmaxf(t0, __shfl_xor_sync(0xffffffffu, t0, 1));
        t0 = fmaxf(t0, __shfl_xor_sync(0xffffffffu, t0, 2));
        t1 = fmaxf(t1, __shfl_xor_sync(0xffffffffu, t1, 1));
        t1 = fmaxf(t1, __shfl_xor_sync(0xffffffffu, t1, 2));
        float n0 = fmaxf(m0, t0), n1 = fmaxf(m1, t1);
        float c0 = __expf(m0 - n0), c1 = __expf(m1 - n1);
        l0 *= c0; l1 *= c1;
        #pragma unroll
        for (int nf = 0; nf < 4; nf++) {
            o[nf][0] *= c0; o[nf][1] *= c0;
            o[nf][2] *= c1; o[nf][3] *= c1;
        }
        m0 = n0; m1 = n1;

        // ---- P = exp(S-m) -> bf16 A-frags (4 k-steps over 64 keys) ----
        uint32_t pa[4][4];
        #pragma unroll
        for (int j2 = 0; j2 < 4; j2++) {
            float p00 = __expf(s[2*j2  ][0] - m0), p01 = __expf(s[2*j2  ][1] - m0);
            float p02 = __expf(s[2*j2  ][2] - m1), p03 = __expf(s[2*j2  ][3] - m1);
            float p10 = __expf(s[2*j2+1][0] - m0), p11 = __expf(s[2*j2+1][1] - m0);
            float p12 = __expf(s[2*j2+1][2] - m1), p13 = __expf(s[2*j2+1][3] - m1);
            l0 += p00 + p01 + p10 + p11;
            l1 += p02 + p03 + p12 + p13;
            pa[j2][0] = packbf(p00, p01);
            pa[j2][1] = packbf(p02, p03);
            pa[j2][2] = packbf(p10, p11);
            pa[j2][3] = packbf(p12, p13);
        }

        // ---- O += P V : 4 d-frags x 4 k-steps ----
        #pragma unroll
        for (int nf = 0; nf < 4; nf++) {
            #pragma unroll
            for (int kk = 0; kk < 4; kk++) {
                const __nv_bfloat16* vr = &Vt[nf*8+g][kk*16 + 2*tig];
                uint32_t b0 = *(const uint32_t*)vr;
                uint32_t b1 = *(const uint32_t*)(vr + 8);
                mma_bf16(o[nf][0], o[nf][1], o[nf][2], o[nf][3],
                         pa[kk][0], pa[kk][1], pa[kk][2], pa[kk][3],
                         b0, b1);
            }
        }
        __syncthreads();
    }

    // ---- finalize: full row sums, normalize, write ----
    l0 += __shfl_xor_sync(0xffffffffu, l0, 1);
    l0 += __shfl_xor_sync(0xffffffffu, l0, 2);
    l1 += __shfl_xor_sync(0xffffffffu, l1, 1);
    l1 += __shfl_xor_sync(0xffffffffu, l1, 2);
    float i0 = 1.f / l0, i1 = 1.f / l1;

    int q0 = rt*64 + w*16 + g;
    float* ob0 = g_att + ((size_t)b_*Nseq + q0)*Cdim + head*Dh;
    float* ob8 = ob0 + 8*Cdim;
    #pragma unroll
    for (int nf = 0; nf < 4; nf++) {
        *(float2*)(ob0 + nf*8 + 2*tig) = make_float2(o[nf][0]*i0, o[nf][1]*i0);
        *(float2*)(ob8 + nf*8 + 2*tig) = make_float2(o[nf][2]*i1, o[nf][3]*i1);
    }
}

// =================================================================
// Kernel 4: out = (att + lepe) @ Wo + bo  -> d_out [9216][256]
// =================================================================
__global__ void out_kernel(const float* __restrict__ Wo, const float* __restrict__ bo,
                           float* __restrict__ out)
{
    __shared__ float As[16][65];
    __shared__ float Bs[16][65];

    const int t  = threadIdx.x;
    const int r0 = blockIdx.y * 64;
    const int c0 = blockIdx.x * 64;
    const int ty = t >> 4, tx = t & 15;

    float acc[4][4] = {};

    for (int k0 = 0; k0 < Cdim; k0 += 16) {
        {
            int m  = t >> 2;
            int kq = (t & 3) * 4;
            size_t off = (size_t)(r0+m)*Cdim + k0 + kq;
            float4 a4 = *(const float4*)(g_att  + off);
            float4 l4 = *(const float4*)(g_lepe + off);
            As[kq+0][m] = a4.x + l4.x; As[kq+1][m] = a4.y + l4.y;
            As[kq+2][m] = a4.z + l4.z; As[kq+3][m] = a4.w + l4.w;
        }
        #pragma unroll
        for (int l = 0; l < 4; l++) {
            int e  = t + l*256;
            int kk = e >> 6, cc = e & 63;
            Bs[kk][cc] = Wo[(size_t)(k0+kk)*Cdim + c0 + cc];
        }
        __syncthreads();
        #pragma unroll
        for (int kk = 0; kk < 16; kk++) {
            float a[4], b[4];
            #pragma unroll
            for (int i = 0; i < 4; i++) a[i] = As[kk][ty*4+i];
            #pragma unroll
            for (int j = 0; j < 4; j++) b[j] = Bs[kk][tx*4+j];
            #pragma unroll
            for (int i = 0; i < 4; i++)
                #pragma unroll
                for (int j = 0; j < 4; j++)
                    acc[i][j] += a[i]*b[j];
        }
        __syncthreads();
    }

    #pragma unroll
    for (int i = 0; i < 4; i++) {
        int r = r0 + ty*4 + i;
        #pragma unroll
        for (int j = 0; j < 4; j++) {
            int c = c0 + tx*4 + j;
            out[(size_t)r*Cdim + c] = acc[i][j] + bo[c];
        }
    }
}

// =================================================================
extern "C" void kernel_launch(void* const* d_in, const int* in_sizes, int n_in,
                              void* d_out, int out_size)
{
    const float* x    = (const float*)d_in[0];
    const float* sn   = (const float*)d_in[1];
    const float* cs   = (const float*)d_in[2];
    const float* mask = (const float*)d_in[3];
    const float* Wq   = (const float*)d_in[4];
    const float* bq   = (const float*)d_in[5];
    const float* Wk   = (const float*)d_in[6];
    const float* bk   = (const float*)d_in[7];
    const float* Wv   = (const float*)d_in[8];
    const float* bv   = (const float*)d_in[9];
    const float* dww  = (const float*)d_in[10];
    const float* dwb  = (const float*)d_in[11];
    const float* Wo   = (const float*)d_in[12];
    const float* bo   = (const float*)d_in[13];

    dim3 g1(Cdim/64, ROWS/64, 3);
    qkv_kernel<<<g1, 256>>>(x, Wq, bq, Wk, bk, Wv, bv, sn, cs);

    lepe_kernel<<<(ROWS*Cdim)/256, 256>>>(dww, dwb);

    dim3 g3(Bsz*(Nseq/64), NH);
    attn_kernel<<<g3, 128>>>(mask);

    dim3 g4(Cdim/64, ROWS/64);
    out_kernel<<<g4, 256>>>(Wo, bo, (float*)d_out);
}

// round 6
// speedup vs baseline: 4.0096x; 1.3339x over previous
#include <cuda_runtime.h>
#include <cuda_bf16.h>
#include <cstdint>

#define Bsz   4
#define Hdim  48
#define Wdim  48
#define Cdim  256
#define NH    8
#define Dh    32
#define Nseq  2304            // 48*48
#define ROWS  9216            // B * Nseq

// ---------------- scratch (no allocations allowed) ----------------
__device__ __nv_bfloat16 g_qh[Bsz*NH*Nseq*Dh];   // head-major bf16 (RoPE'd)
__device__ __nv_bfloat16 g_kh[Bsz*NH*Nseq*Dh];   // head-major bf16 (RoPE'd, pre-scaled)
__device__ __nv_bfloat16 g_vh[Bsz*NH*Nseq*Dh];   // head-major bf16
__device__ float g_v   [Bsz*NH*Nseq*Dh];         // fp32 V for LePE
__device__ float g_lepe[ROWS*Cdim];              // [b*n][c]
__device__ float g_att [ROWS*Cdim];              // [b*n][c]

// ---------------- helpers ----------------
__device__ __forceinline__ void mma_bf16(float& d0, float& d1, float& d2, float& d3,
                                         uint32_t a0, uint32_t a1, uint32_t a2, uint32_t a3,
                                         uint32_t b0, uint32_t b1)
{
    asm volatile("mma.sync.aligned.m16n8k16.row.col.f32.bf16.bf16.f32 "
                 "{%0,%1,%2,%3}, {%4,%5,%6,%7}, {%8,%9}, {%0,%1,%2,%3};"
                 : "+f"(d0), "+f"(d1), "+f"(d2), "+f"(d3)
                 : "r"(a0), "r"(a1), "r"(a2), "r"(a3), "r"(b0), "r"(b1));
}

__device__ __forceinline__ void mma_tf32(float& d0, float& d1, float& d2, float& d3,
                                         uint32_t a0, uint32_t a1, uint32_t a2, uint32_t a3,
                                         uint32_t b0, uint32_t b1)
{
    asm volatile("mma.sync.aligned.m16n8k8.row.col.f32.tf32.tf32.f32 "
                 "{%0,%1,%2,%3}, {%4,%5,%6,%7}, {%8,%9}, {%0,%1,%2,%3};"
                 : "+f"(d0), "+f"(d1), "+f"(d2), "+f"(d3)
                 : "r"(a0), "r"(a1), "r"(a2), "r"(a3), "r"(b0), "r"(b1));
}

__device__ __forceinline__ uint32_t f2tf(float f)
{
    uint32_t r;
    asm("cvt.rna.tf32.f32 %0, %1;" : "=r"(r) : "f"(f));
    return r;
}

__device__ __forceinline__ uint32_t packbf(float lo, float hi)
{
    uint32_t r;
    asm("cvt.rn.bf16x2.f32 %0, %1, %2;" : "=r"(r) : "f"(hi), "f"(lo));
    return r;
}

// =================================================================
// Kernel 1: tf32 tensor-core Q/K/V GEMM + bias + k-scale + RoPE.
//   tile 128 rows x 64 cols, 8 warps. A:[128][36] B:[32][72] staging.
// =================================================================
__global__ void __launch_bounds__(256) qkv_tc(const float* __restrict__ x,
                           const float* __restrict__ Wq, const float* __restrict__ bq,
                           const float* __restrict__ Wk, const float* __restrict__ bk,
                           const float* __restrict__ Wv, const float* __restrict__ bv,
                           const float* __restrict__ sn, const float* __restrict__ cs)
{
    const int which = blockIdx.z;                  // 0=q 1=k 2=v
    const float* Wm = (which==0) ? Wq : (which==1 ? Wk : Wv);
    const float* bm = (which==0) ? bq : (which==1 ? bk : bv);

    __shared__ float Xs[128][36];
    __shared__ float Ws[32][72];

    const int t    = threadIdx.x;
    const int w    = t >> 5;
    const int lane = t & 31;
    const int g    = lane >> 2;
    const int tig  = lane & 3;
    const int r0   = blockIdx.y * 128;
    const int c0   = blockIdx.x * 64;

    float acc[8][4] = {};

    for (int k0 = 0; k0 < Cdim; k0 += 32) {
        #pragma unroll
        for (int l = 0; l < 4; l++) {              // A: 128x32
            int f4 = t + l*256;
            int row = f4 >> 3, c4 = (f4 & 7) * 4;
            float4 v = *(const float4*)(x + (size_t)(r0+row)*Cdim + k0 + c4);
            Xs[row][c4+0] = v.x; Xs[row][c4+1] = v.y;
            Xs[row][c4+2] = v.z; Xs[row][c4+3] = v.w;
        }
        #pragma unroll
        for (int l = 0; l < 2; l++) {              // B: 32x64
            int f4 = t + l*256;
            int row = f4 >> 4, c4 = (f4 & 15) * 4;
            float4 v = *(const float4*)(Wm + (size_t)(k0+row)*Cdim + c0 + c4);
            Ws[row][c4+0] = v.x; Ws[row][c4+1] = v.y;
            Ws[row][c4+2] = v.z; Ws[row][c4+3] = v.w;
        }
        __syncthreads();

        #pragma unroll
        for (int ks = 0; ks < 4; ks++) {           // 4 k-steps of 8
            int kk = ks*8;
            uint32_t a0 = f2tf(Xs[w*16+g  ][kk+tig  ]);
            uint32_t a1 = f2tf(Xs[w*16+g+8][kk+tig  ]);
            uint32_t a2 = f2tf(Xs[w*16+g  ][kk+tig+4]);
            uint32_t a3 = f2tf(Xs[w*16+g+8][kk+tig+4]);
            #pragma unroll
            for (int nf = 0; nf < 8; nf++) {
                uint32_t b0 = f2tf(Ws[kk+tig  ][nf*8+g]);
                uint32_t b1 = f2tf(Ws[kk+tig+4][nf*8+g]);
                mma_tf32(acc[nf][0], acc[nf][1], acc[nf][2], acc[nf][3],
                         a0, a1, a2, a3, b0, b1);
            }
        }
        __syncthreads();
    }

    // ---- epilogue: bias + k-scale + RoPE + head-major writes ----
    const float scaling = 0.17677669529663687f;
    const int rg  = r0 + w*16 + g;                 // tile never straddles batch
    const int b_  = rg / Nseq;
    const int n0  = rg % Nseq;                     // row g
    const int n8  = n0 + 8;                        // row g+8
    #pragma unroll
    for (int nf = 0; nf < 8; nf++) {
        int ce = c0 + nf*8 + 2*tig;                // even col, pair (ce, ce+1)
        int de = ce & 31;
        int head = ce >> 5;
        #pragma unroll
        for (int half = 0; half < 2; half++) {     // 0: row g, 1: row g+8
            int   n  = half ? n8 : n0;
            float ve = acc[nf][half*2+0] + bm[ce];
            float vo = acc[nf][half*2+1] + bm[ce+1];
            if (which == 1) { ve *= scaling; vo *= scaling; }
            if (which < 2) {
                int sbase = n * Dh;
                float se = sn[sbase+de],   c_e = cs[sbase+de];
                float so = sn[sbase+de+1], c_o = cs[sbase+de+1];
                float oe = ve*c_e - vo*se;
                float oo = vo*c_o + ve*so;
                ve = oe; vo = oo;
            }
            size_t idx = ((size_t)(b_*NH + head)*Nseq + n)*Dh + de;
            __nv_bfloat162 h;
            h.x = __float2bfloat16_rn(ve);
            h.y = __float2bfloat16_rn(vo);
            if (which == 0)      *(__nv_bfloat162*)(g_qh + idx) = h;
            else if (which == 1) *(__nv_bfloat162*)(g_kh + idx) = h;
            else {
                *(float2*)(g_v + idx) = make_float2(ve, vo);
                *(__nv_bfloat162*)(g_vh + idx) = h;
            }
        }
    }
}

// =================================================================
// Kernel 2: LePE — depthwise 5x5 conv over V (zero pad 2), + bias.
// =================================================================
__global__ void lepe_kernel(const float* __restrict__ dww, const float* __restrict__ dwb)
{
    int idx = blockIdx.x * blockDim.x + threadIdx.x;   // over ROWS*Cdim
    int c  = idx & 255;
    int p  = idx >> 8;
    int b_ = p / Nseq;
    int n  = p % Nseq;
    int hp = n / Wdim, wp = n % Wdim;
    int head = c >> 5, dd = c & 31;
    const float* vbase = g_v + ((size_t)(b_*NH + head)*Nseq)*Dh + dd;

    float acc = dwb[c];
    #pragma unroll
    for (int ky = 0; ky < 5; ky++) {
        int hh = hp + ky - 2;
        if (hh < 0 || hh >= Hdim) continue;
        #pragma unroll
        for (int kx = 0; kx < 5; kx++) {
            int ww = wp + kx - 2;
            if (ww < 0 || ww >= Wdim) continue;
            acc += vbase[(size_t)(hh*Wdim + ww)*Dh] * dww[(ky*5 + kx)*Cdim + c];
        }
    }
    g_lepe[idx] = acc;
}

// =================================================================
// Kernel 3: flash attention, bf16 tensor-core mma (m16n8k16).
//   (unchanged from R5 passing version)
// =================================================================
__global__ void __launch_bounds__(128) attn_kernel(const float* __restrict__ mask)
{
    const int bx   = blockIdx.x;
    const int b_   = bx & 3;         // batch fastest -> mask L2 reuse across b
    const int rt   = bx >> 2;        // 0..35 q-row tile
    const int head = blockIdx.y;
    const int t    = threadIdx.x;
    const int w    = t >> 5;         // warp 0..3
    const int lane = t & 31;
    const int g    = lane >> 2;      // 0..7
    const int tig  = lane & 3;       // 0..3

    __shared__ __align__(16) __nv_bfloat16 Qs[64][36];
    __shared__ __align__(16) __nv_bfloat16 Ks[64][36];
    __shared__ __align__(16) __nv_bfloat16 Vt[32][72];

    const size_t hb = (size_t)(b_*NH + head);
    const uint32_t* qg  = (const uint32_t*)(g_qh + (hb*Nseq + (size_t)rt*64)*Dh);
    const uint32_t* kg0 = (const uint32_t*)(g_kh + hb*Nseq*Dh);
    const uint32_t* vg0 = (const uint32_t*)(g_vh + hb*Nseq*Dh);
    const float* mrow0 = mask + ((size_t)head*Nseq + rt*64 + w*16 + g)*Nseq;
    const float* mrow8 = mrow0 + 8*(size_t)Nseq;

    // ---- stage Q once ----
    uint32_t* qs_u = (uint32_t*)Qs;            // row stride 18 u32
    uint32_t* ks_u = (uint32_t*)Ks;
    #pragma unroll
    for (int l = 0; l < 8; l++) {
        int e = t + l*128;
        qs_u[(e >> 4)*18 + (e & 15)] = qg[e];
    }
    __syncthreads();

    // Q A-fragments (2 k-steps of 16 over d=32)
    uint32_t qa[2][4];
    #pragma unroll
    for (int ks = 0; ks < 2; ks++) {
        const uint32_t* r0 = qs_u + (w*16+g  )*18 + ks*8 + tig;
        const uint32_t* r8 = qs_u + (w*16+g+8)*18 + ks*8 + tig;
        qa[ks][0] = r0[0]; qa[ks][1] = r8[0];
        qa[ks][2] = r0[4]; qa[ks][3] = r8[4];
    }

    float o[4][4] = {};                  // O: 4 d-frags (m16n8), fp32
    float m0 = -1e30f, m1 = -1e30f;
    float l0 = 0.f,    l1 = 0.f;

    for (int kt = 0; kt < Nseq/64; kt++) {
        // ---- mask tile -> accumulator init (C of the S mma) ----
        float s[8][4];
        #pragma unroll
        for (int j = 0; j < 8; j++) {
            float2 mA = *(const float2*)(mrow0 + (size_t)kt*64 + j*8 + 2*tig);
            float2 mB = *(const float2*)(mrow8 + (size_t)kt*64 + j*8 + 2*tig);
            s[j][0] = mA.x; s[j][1] = mA.y; s[j][2] = mB.x; s[j][3] = mB.y;
        }
        // ---- stage K (row-major) and V (transposed) ----
        const uint32_t* kg = kg0 + (size_t)kt*64*16;
        const uint32_t* vg = vg0 + (size_t)kt*64*16;
        #pragma unroll
        for (int l = 0; l < 8; l++) {
            int e   = t + l*128;
            int row = e >> 4, dp = e & 15;
            ks_u[row*18 + dp] = kg[e];
            uint32_t vv = vg[e];
            __nv_bfloat162 v2 = *(__nv_bfloat162*)&vv;
            Vt[2*dp  ][row] = v2.x;
            Vt[2*dp+1][row] = v2.y;
        }
        __syncthreads();

        // ---- S = Q K^T + mask ----
        #pragma unroll
        for (int j = 0; j < 8; j++) {
            #pragma unroll
            for (int ks = 0; ks < 2; ks++) {
                const uint32_t* kr = ks_u + (j*8+g)*18 + ks*8 + tig;
                mma_bf16(s[j][0], s[j][1], s[j][2], s[j][3],
                         qa[ks][0], qa[ks][1], qa[ks][2], qa[ks][3],
                         kr[0], kr[4]);
            }
        }

        // ---- online softmax ----
        float t0 = -1e30f, t1 = -1e30f;
        #pragma unroll
        for (int j = 0; j < 8; j++) {
            t0 = fmaxf(t0, fmaxf(s[j][0], s[j][1]));
            t1 = fmaxf(t1, fmaxf(s[j][2], s[j][3]));
        }
        t0 = fmaxf(t0, __shfl_xor_sync(0xffffffffu, t0, 1));
        t0 = fmaxf(t0, __shfl_xor_sync(0xffffffffu, t0, 2));
        t1 = fmaxf(t1, __shfl_xor_sync(0xffffffffu, t1, 1));
        t1 = fmaxf(t1, __shfl_xor_sync(0xffffffffu, t1, 2));
        float n0 = fmaxf(m0, t0), n1 = fmaxf(m1, t1);
        float c0 = __expf(m0 - n0), c1 = __expf(m1 - n1);
        l0 *= c0; l1 *= c1;
        #pragma unroll
        for (int nf = 0; nf < 4; nf++) {
            o[nf][0] *= c0; o[nf][1] *= c0;
            o[nf][2] *= c1; o[nf][3] *= c1;
        }
        m0 = n0; m1 = n1;

        // ---- P = exp(S-m) -> bf16 A-frags ----
        uint32_t pa[4][4];
        #pragma unroll
        for (int j2 = 0; j2 < 4; j2++) {
            float p00 = __expf(s[2*j2  ][0] - m0), p01 = __expf(s[2*j2  ][1] - m0);
            float p02 = __expf(s[2*j2  ][2] - m1), p03 = __expf(s[2*j2  ][3] - m1);
            float p10 = __expf(s[2*j2+1][0] - m0), p11 = __expf(s[2*j2+1][1] - m0);
            float p12 = __expf(s[2*j2+1][2] - m1), p13 = __expf(s[2*j2+1][3] - m1);
            l0 += p00 + p01 + p10 + p11;
            l1 += p02 + p03 + p12 + p13;
            pa[j2][0] = packbf(p00, p01);
            pa[j2][1] = packbf(p02, p03);
            pa[j2][2] = packbf(p10, p11);
            pa[j2][3] = packbf(p12, p13);
        }

        // ---- O += P V ----
        #pragma unroll
        for (int nf = 0; nf < 4; nf++) {
            #pragma unroll
            for (int kk = 0; kk < 4; kk++) {
                const __nv_bfloat16* vr = &Vt[nf*8+g][kk*16 + 2*tig];
                uint32_t b0 = *(const uint32_t*)vr;
                uint32_t b1 = *(const uint32_t*)(vr + 8);
                mma_bf16(o[nf][0], o[nf][1], o[nf][2], o[nf][3],
                         pa[kk][0], pa[kk][1], pa[kk][2], pa[kk][3],
                         b0, b1);
            }
        }
        __syncthreads();
    }

    // ---- finalize ----
    l0 += __shfl_xor_sync(0xffffffffu, l0, 1);
    l0 += __shfl_xor_sync(0xffffffffu, l0, 2);
    l1 += __shfl_xor_sync(0xffffffffu, l1, 1);
    l1 += __shfl_xor_sync(0xffffffffu, l1, 2);
    float i0 = 1.f / l0, i1 = 1.f / l1;

    int q0 = rt*64 + w*16 + g;
    float* ob0 = g_att + ((size_t)b_*Nseq + q0)*Cdim + head*Dh;
    float* ob8 = ob0 + 8*Cdim;
    #pragma unroll
    for (int nf = 0; nf < 4; nf++) {
        *(float2*)(ob0 + nf*8 + 2*tig) = make_float2(o[nf][0]*i0, o[nf][1]*i0);
        *(float2*)(ob8 + nf*8 + 2*tig) = make_float2(o[nf][2]*i1, o[nf][3]*i1);
    }
}

// =================================================================
// Kernel 4: tf32 TC GEMM: out = (att + lepe) @ Wo + bo
// =================================================================
__global__ void __launch_bounds__(256) out_tc(const float* __restrict__ Wo,
                                              const float* __restrict__ bo,
                                              float* __restrict__ out)
{
    __shared__ float Xs[128][36];
    __shared__ float Ws[32][72];

    const int t    = threadIdx.x;
    const int w    = t >> 5;
    const int lane = t & 31;
    const int g    = lane >> 2;
    const int tig  = lane & 3;
    const int r0   = blockIdx.y * 128;
    const int c0   = blockIdx.x * 64;

    float acc[8][4] = {};

    for (int k0 = 0; k0 < Cdim; k0 += 32) {
        #pragma unroll
        for (int l = 0; l < 4; l++) {              // A: (att+lepe) 128x32
            int f4 = t + l*256;
            int row = f4 >> 3, c4 = (f4 & 7) * 4;
            size_t off = (size_t)(r0+row)*Cdim + k0 + c4;
            float4 a = *(const float4*)(g_att  + off);
            float4 b = *(const float4*)(g_lepe + off);
            Xs[row][c4+0] = a.x + b.x; Xs[row][c4+1] = a.y + b.y;
            Xs[row][c4+2] = a.z + b.z; Xs[row][c4+3] = a.w + b.w;
        }
        #pragma unroll
        for (int l = 0; l < 2; l++) {              // B: Wo 32x64
            int f4 = t + l*256;
            int row = f4 >> 4, c4 = (f4 & 15) * 4;
            float4 v = *(const float4*)(Wo + (size_t)(k0+row)*Cdim + c0 + c4);
            Ws[row][c4+0] = v.x; Ws[row][c4+1] = v.y;
            Ws[row][c4+2] = v.z; Ws[row][c4+3] = v.w;
        }
        __syncthreads();

        #pragma unroll
        for (int ks = 0; ks < 4; ks++) {
            int kk = ks*8;
            uint32_t a0 = f2tf(Xs[w*16+g  ][kk+tig  ]);
            uint32_t a1 = f2tf(Xs[w*16+g+8][kk+tig  ]);
            uint32_t a2 = f2tf(Xs[w*16+g  ][kk+tig+4]);
            uint32_t a3 = f2tf(Xs[w*16+g+8][kk+tig+4]);
            #pragma unroll
            for (int nf = 0; nf < 8; nf++) {
                uint32_t b0 = f2tf(Ws[kk+tig  ][nf*8+g]);
                uint32_t b1 = f2tf(Ws[kk+tig+4][nf*8+g]);
                mma_tf32(acc[nf][0], acc[nf][1], acc[nf][2], acc[nf][3],
                         a0, a1, a2, a3, b0, b1);
            }
        }
        __syncthreads();
    }

    const int rg = r0 + w*16 + g;
    #pragma unroll
    for (int nf = 0; nf < 8; nf++) {
        int ce = c0 + nf*8 + 2*tig;
        float2 bb = make_float2(bo[ce], bo[ce+1]);
        *(float2*)(out + (size_t)rg*Cdim + ce) =
            make_float2(acc[nf][0] + bb.x, acc[nf][1] + bb.y);
        *(float2*)(out + (size_t)(rg+8)*Cdim + ce) =
            make_float2(acc[nf][2] + bb.x, acc[nf][3] + bb.y);
    }
}

// =================================================================
extern "C" void kernel_launch(void* const* d_in, const int* in_sizes, int n_in,
                              void* d_out, int out_size)
{
    const float* x    = (const float*)d_in[0];
    const float* sn   = (const float*)d_in[1];
    const float* cs   = (const float*)d_in[2];
    const float* mask = (const float*)d_in[3];
    const float* Wq   = (const float*)d_in[4];
    const float* bq   = (const float*)d_in[5];
    const float* Wk   = (const float*)d_in[6];
    const float* bk   = (const float*)d_in[7];
    const float* Wv   = (const float*)d_in[8];
    const float* bv   = (const float*)d_in[9];
    const float* dww  = (const float*)d_in[10];
    const float* dwb  = (const float*)d_in[11];
    const float* Wo   = (const float*)d_in[12];
    const float* bo   = (const float*)d_in[13];

    dim3 g1(Cdim/64, ROWS/128, 3);
    qkv_tc<<<g1, 256>>>(x, Wq, bq, Wk, bk, Wv, bv, sn, cs);

    lepe_kernel<<<(ROWS*Cdim)/256, 256>>>(dww, dwb);

    dim3 g3(Bsz*(Nseq/64), NH);
    attn_kernel<<<g3, 128>>>(mask);

    dim3 g4(Cdim/64, ROWS/128);
    out_tc<<<g4, 256>>>(Wo, bo, (float*)d_out);
}